// round 15
// baseline (speedup 1.0000x reference)
#include <cuda_runtime.h>
#include <cuda_bf16.h>
#include <math.h>
#include <stdint.h>

// ---------------- problem constants ----------------
constexpr int HI = 256, WI = 256;
constexpr int HL = 64,  WL = 64;
constexpr int MB  = 4096;     // m-blocks of 128 rows (524288 rows total)
constexpr int CH  = 256;      // m-blocks per chunk (static scratch ~292 MB)
constexpr int NTH = 256;

#define DEVINL __device__ __forceinline__

// ---------------- activation images (A-fragment blob order), per-chunk ----------------
// blob (per m-block per k64 chunk) = [kt(4)][row(128)][kpair(8)] u32 hi plane (4096 u32),
// then lo plane (+4096). blob = 8192 u32 = 32 KB.
__device__ uint32_t X0I[(size_t)CH * 7  * 8192];   // 57 MB
__device__ uint32_t X1I[(size_t)CH * 16 * 8192];   // 134 MB
__device__ uint32_t X2I[(size_t)CH * 8  * 8192];   // 67 MB
__device__ uint32_t X3I[(size_t)CH * 4  * 8192];   // 34 MB

// ---------------- weight blobs (B-fragment order) ----------------
// chunk (per nb per kc) = [nt][kt(4)][lane(32)] uint4(hi_b0,hi_b1,lo_b0,lo_b1)
__device__ uint4 W1B[4 * 7  * 32 * 4 * 32];
__device__ uint4 W2B[2 * 16 * 32 * 4 * 32];
__device__ uint4 W3B[1 * 8  * 32 * 4 * 32];
__device__ uint4 W4B[1 * 4  * 16 * 4 * 32];

// ---------------- helpers ----------------
DEVINL void split2(float x, uint16_t& h, uint16_t& l) {
    __nv_bfloat16 hb = __float2bfloat16(x);
    float r = x - __bfloat162float(hb);
    __nv_bfloat16 lb = __float2bfloat16(r);
    h = __bfloat16_as_ushort(hb);
    l = __bfloat16_as_ushort(lb);
}

DEVINL void mma16816(float* d, const uint32_t* a, uint32_t b0, uint32_t b1) {
    asm("mma.sync.aligned.m16n8k16.row.col.f32.bf16.bf16.f32 "
        "{%0,%1,%2,%3}, {%4,%5,%6,%7}, {%8,%9}, {%0,%1,%2,%3};"
        : "+f"(d[0]), "+f"(d[1]), "+f"(d[2]), "+f"(d[3])
        : "r"(a[0]), "r"(a[1]), "r"(a[2]), "r"(a[3]), "r"(b0), "r"(b1));
}

DEVINL uint32_t smem_u32(const void* p) {
    uint32_t a;
    asm("{ .reg .u64 t; cvta.to.shared.u64 t, %1; cvt.u32.u64 %0, t; }" : "=r"(a) : "l"(p));
    return a;
}

DEVINL void cpa16(uint32_t s, const void* g) {
    asm volatile("cp.async.cg.shared.global [%0], [%1], 16;" :: "r"(s), "l"(g) : "memory");
}
DEVINL void cpa_commit() { asm volatile("cp.async.commit_group;" ::: "memory"); }
template<int N> DEVINL void cpa_wait() { asm volatile("cp.async.wait_group %0;" :: "n"(N) : "memory"); }

// ---------------- weight prep: fp32 [K,N] -> fragment blob images ----------------
__global__ void prep_w(const float* __restrict__ W, int K, int N, int NB, int NT, int KC, int sel) {
    uint4* dst = (sel == 1) ? W1B : (sel == 2) ? W2B : (sel == 3) ? W3B : W4B;
    int total = NB * KC * NT * 4 * 32;
    int idx = blockIdx.x * blockDim.x + threadIdx.x;
    if (idx >= total) return;
    int lane = idx & 31;
    int t = idx >> 5;
    int kt = t & 3;  t >>= 2;
    int nt = t % NT; t /= NT;
    int kc = t % KC;
    int nbb = t / KC;
    int n = nbb * NT * 8 + nt * 8 + (lane >> 2);
    int k0 = kc * 64 + kt * 16 + (lane & 3) * 2;
    int ks[4] = {k0, k0 + 1, k0 + 8, k0 + 9};
    uint16_t h[4], l[4];
    #pragma unroll
    for (int i = 0; i < 4; ++i) {
        float v = (ks[i] < K) ? W[(size_t)ks[i] * N + n] : 0.0f;
        split2(v, h[i], l[i]);
    }
    dst[idx] = make_uint4((uint32_t)h[0] | ((uint32_t)h[1] << 16),
                          (uint32_t)h[2] | ((uint32_t)h[3] << 16),
                          (uint32_t)l[0] | ((uint32_t)l[1] << 16),
                          (uint32_t)l[2] | ((uint32_t)l[3] << 16));
}

// ---------------- gather kernel: build X0 image for one chunk ----------------
__global__ __launch_bounds__(NTH, 1)
void gather_k(const float* __restrict__ feat, const float* __restrict__ coord,
              const float* __restrict__ hr, const float* __restrict__ lr, int mb0)
{
    const int tid = threadIdx.x, lane = tid & 31, warp = tid >> 5;
    const int mb = blockIdx.x;                 // local m-block within chunk
    uint32_t* dst = X0I + (size_t)mb * 7 * 8192;

    for (int rr = 0; rr < 16; ++rr) {
        int row = warp * 16 + rr;              // 0..127
        int grow = (mb0 + mb) * 128 + row;
        int p = grow >> 2, br = grow & 3, b = p >> 16;

        float y = coord[(size_t)p * 2 + 0];
        float x = coord[(size_t)p * 2 + 1];

        int ihy = (int)floorf((y + 1.0f) * (0.5f * HI));
        int ihx = (int)floorf((x + 1.0f) * (0.5f * WI));
        bool vh = (ihy >= 0) & (ihy < HI) & (ihx >= 0) & (ihx < WI);
        int ihyc = min(max(ihy, 0), HI - 1);
        int ihxc = min(max(ihx, 0), WI - 1);

        float vx = (br & 2) ? 1.0f : -1.0f;
        float vy = (br & 1) ? 1.0f : -1.0f;
        float cy = y + vx * (1.0f / (float)HL);
        float cx = x + vy * (1.0f / (float)WL);
        int iy = (int)floorf((cy + 1.0f) * (0.5f * HL));
        int ix = (int)floorf((cx + 1.0f) * (0.5f * WL));
        bool v = (iy >= 0) & (iy < HL) & (ix >= 0) & (ix < WL);
        int iyc = min(max(iy, 0), HL - 1);
        int ixc = min(max(ix, 0), WL - 1);

        float qy = v ? (-1.0f + (2 * iyc + 1) * (1.0f / (float)HL)) : 0.0f;
        float qx = v ? (-1.0f + (2 * ixc + 1) * (1.0f / (float)WL)) : 0.0f;
        float rel_y = (y - qy) * (float)HL;
        float rel_x = (x - qx) * (float)WL;

        const float* featb = feat + (size_t)b * 128 * 4096;
        const float* hrb   = hr   + (size_t)b * 128 * 65536;
        const float* lrb   = lr   + (size_t)b * 128 * 4096;
        int fidx = iyc * WL + ixc;
        int hidx = ihyc * WI + ihxc;

        for (int pr = lane; pr < 224; pr += 32) {
            int k0 = pr * 2;
            float v0, v1;
            if (k0 < 128) {
                v0 = v ? featb[k0 * 4096 + fidx]       : 0.0f;
                v1 = v ? featb[(k0 + 1) * 4096 + fidx] : 0.0f;
            } else if (k0 < 256) {
                int c = k0 - 128;
                v0 = vh ? hrb[c * 65536 + hidx]       : 0.0f;
                v1 = vh ? hrb[(c + 1) * 65536 + hidx] : 0.0f;
            } else if (k0 < 384) {
                int c = k0 - 256;
                float a0 = vh ? hrb[c * 65536 + hidx]       : 0.0f;
                float a1 = vh ? hrb[(c + 1) * 65536 + hidx] : 0.0f;
                v0 = a0 - (v ? lrb[c * 4096 + fidx]       : 0.0f);
                v1 = a1 - (v ? lrb[(c + 1) * 4096 + fidx] : 0.0f);
            } else if (k0 == 384) {
                v0 = rel_y; v1 = rel_x;
            } else {
                v0 = 0.0f; v1 = 0.0f;
            }
            uint16_t h0, l0, h1, l1;
            split2(v0, h0, l0);
            split2(v1, h1, l1);
            int kc = pr >> 5, pp = pr & 31, kt = pp >> 3, kp = pp & 7;
            size_t idx = (size_t)kc * 8192 + kt * 1024 + row * 8 + kp;
            dst[idx]        = (uint32_t)h0 | ((uint32_t)h1 << 16);
            dst[idx + 4096] = (uint32_t)l0 | ((uint32_t)l1 << 16);
        }
    }
}

// ---------------- layer kernel: M=128 rows/CTA, cp.async double-buffered ----------------
template<int LAYER>
__global__ __launch_bounds__(NTH, 1)
void layer_k(const float* __restrict__ bias, const float* __restrict__ w5,
             const float* __restrict__ b5, float* __restrict__ out, int mb0)
{
    constexpr int KC     = (LAYER == 1) ? 7 : (LAYER == 2) ? 16 : (LAYER == 3) ? 8 : 4;
    constexpr int NT     = (LAYER == 4) ? 16 : 32;
    constexpr int KCOUT  = (LAYER == 1) ? 16 : (LAYER == 2) ? 8 : (LAYER == 3) ? 4 : 0;
    constexpr int WCH_U4 = NT * 4 * 32;           // uint4 per weight chunk
    constexpr int SLOT   = 32768 + WCH_U4 * 16;   // A blob + W chunk bytes

    extern __shared__ uint8_t smem[];
    const int tid = threadIdx.x, lane = tid & 31, warp = tid >> 5;
    const int t4 = lane & 3, g = lane >> 2;
    const int mb = blockIdx.x, nb = blockIdx.y;
    const int wr = warp * 16;

    const uint32_t* Xin = (LAYER == 1) ? X0I : (LAYER == 2) ? X1I : (LAYER == 3) ? X2I : X3I;
    uint32_t* Xout      = (LAYER == 1) ? X1I : (LAYER == 2) ? X2I : X3I;
    const uint4* Wb     = (LAYER == 1) ? W1B : (LAYER == 2) ? W2B : (LAYER == 3) ? W3B : W4B;

    const uint32_t* XinMb = Xin + (size_t)mb * KC * 8192;
    const uint4* Wnb = Wb + (size_t)nb * KC * WCH_U4;

    float*  sbias = (float*)(smem + 2 * SLOT);
    float*  sw5   = (float*)(smem + 2 * SLOT + 1024);
    float2* shead = (float2*)(smem + 2 * SLOT + 2048);

    if (tid < NT * 8) sbias[tid] = bias[nb * NT * 8 + tid];
    if (LAYER == 4 && tid < 256) sw5[tid] = w5[tid];

    const uint32_t sb = smem_u32(smem);

    auto stage = [&](int kc, int s) {
        uint32_t sA = sb + s * SLOT;
        const uint4* gA = (const uint4*)(XinMb + (size_t)kc * 8192);
        #pragma unroll
        for (int i = 0; i < 8; ++i)
            cpa16(sA + (tid + i * 256) * 16, gA + tid + i * 256);
        uint32_t sW = sA + 32768;
        const uint4* gW = Wnb + (size_t)kc * WCH_U4;
        #pragma unroll
        for (int i = 0; i < WCH_U4 / 256; ++i)
            cpa16(sW + (tid + i * 256) * 16, gW + tid + i * 256);
    };

    float acc[NT][4];
    #pragma unroll
    for (int nt = 0; nt < NT; ++nt) {
        acc[nt][0] = 0.f; acc[nt][1] = 0.f; acc[nt][2] = 0.f; acc[nt][3] = 0.f;
    }

    stage(0, 0);
    cpa_commit();

    #pragma unroll 1
    for (int kc = 0; kc < KC; ++kc) {
        const int s = kc & 1;
        if (kc + 1 < KC) { stage(kc + 1, s ^ 1); cpa_commit(); cpa_wait<1>(); }
        else             { cpa_wait<0>(); }
        __syncthreads();

        const uint32_t* sA = (const uint32_t*)(smem + s * SLOT);
        const uint4*    sW = (const uint4*)(smem + s * SLOT + 32768);

        #pragma unroll
        for (int kt = 0; kt < 4; ++kt) {
            const uint32_t* pa = sA + kt * 1024 + wr * 8;
            uint32_t ah[4], al[4];
            ah[0] = pa[g * 8 + t4];
            ah[1] = pa[(g + 8) * 8 + t4];
            ah[2] = pa[g * 8 + t4 + 4];
            ah[3] = pa[(g + 8) * 8 + t4 + 4];
            const uint32_t* pl = pa + 4096;
            al[0] = pl[g * 8 + t4];
            al[1] = pl[(g + 8) * 8 + t4];
            al[2] = pl[g * 8 + t4 + 4];
            al[3] = pl[(g + 8) * 8 + t4 + 4];
            #pragma unroll
            for (int nt = 0; nt < NT; ++nt) {
                uint4 wv = sW[(nt * 4 + kt) * 32 + lane];
                mma16816(acc[nt], ah, wv.x, wv.y);   // hi*hi
                mma16816(acc[nt], ah, wv.z, wv.w);   // hi*lo
                mma16816(acc[nt], al, wv.x, wv.y);   // lo*hi
            }
        }
        __syncthreads();
    }

    if (LAYER != 4) {
        uint32_t* Xo = Xout + (size_t)mb * KCOUT * 8192;
        #pragma unroll
        for (int nt = 0; nt < NT; ++nt) {
            int cb = nt * 8 + t4 * 2;
            float b0 = sbias[cb], b1 = sbias[cb + 1];
            float v0 = fmaxf(acc[nt][0] + b0, 0.f), v1 = fmaxf(acc[nt][1] + b1, 0.f);
            float v2 = fmaxf(acc[nt][2] + b0, 0.f), v3 = fmaxf(acc[nt][3] + b1, 0.f);
            uint16_t h0, l0, h1, l1, h2, l2, h3, l3;
            split2(v0, h0, l0); split2(v1, h1, l1);
            split2(v2, h2, l2); split2(v3, h3, l3);
            int gk = nb * 256 + cb;
            int kc_o = gk >> 6, c64 = gk & 63;
            int kt_o = c64 >> 4, kp_o = (c64 & 15) >> 1;
            size_t base = (size_t)kc_o * 8192 + kt_o * 1024 + kp_o;
            Xo[base + (wr + g) * 8]            = (uint32_t)h0 | ((uint32_t)h1 << 16);
            Xo[base + 4096 + (wr + g) * 8]     = (uint32_t)l0 | ((uint32_t)l1 << 16);
            Xo[base + (wr + g + 8) * 8]        = (uint32_t)h2 | ((uint32_t)h3 << 16);
            Xo[base + 4096 + (wr + g + 8) * 8] = (uint32_t)l2 | ((uint32_t)l3 << 16);
        }
    } else {
        // fused 128->2 head: per-thread partial dot over its cols, rows wr+g / wr+g+8
        float p0a = 0.f, p1a = 0.f, p0b = 0.f, p1b = 0.f;
        #pragma unroll
        for (int nt = 0; nt < NT; ++nt) {
            int cb = nt * 8 + t4 * 2;
            float x0 = fmaxf(acc[nt][0] + sbias[cb],     0.f);
            float x1 = fmaxf(acc[nt][1] + sbias[cb + 1], 0.f);
            float x2 = fmaxf(acc[nt][2] + sbias[cb],     0.f);
            float x3 = fmaxf(acc[nt][3] + sbias[cb + 1], 0.f);
            p0a += x0 * sw5[cb * 2]     + x1 * sw5[(cb + 1) * 2];
            p1a += x0 * sw5[cb * 2 + 1] + x1 * sw5[(cb + 1) * 2 + 1];
            p0b += x2 * sw5[cb * 2]     + x3 * sw5[(cb + 1) * 2];
            p1b += x2 * sw5[cb * 2 + 1] + x3 * sw5[(cb + 1) * 2 + 1];
        }
        // reduce over the 4 t4 lanes
        p0a += __shfl_xor_sync(0xffffffff, p0a, 1); p0a += __shfl_xor_sync(0xffffffff, p0a, 2);
        p1a += __shfl_xor_sync(0xffffffff, p1a, 1); p1a += __shfl_xor_sync(0xffffffff, p1a, 2);
        p0b += __shfl_xor_sync(0xffffffff, p0b, 1); p0b += __shfl_xor_sync(0xffffffff, p0b, 2);
        p1b += __shfl_xor_sync(0xffffffff, p1b, 1); p1b += __shfl_xor_sync(0xffffffff, p1b, 2);
        if (t4 == 0) {
            shead[wr + g]     = make_float2(p0a + b5[0], p1a + b5[1]);
            shead[wr + g + 8] = make_float2(p0b + b5[0], p1b + b5[1]);
        }
        __syncthreads();
        if (tid < 32) {
            float2 r0 = shead[tid * 4 + 0], r1 = shead[tid * 4 + 1];
            float2 r2 = shead[tid * 4 + 2], r3 = shead[tid * 4 + 3];
            float m = fmaxf(fmaxf(r0.y, r1.y), fmaxf(r2.y, r3.y));
            float e0 = expf(r0.y - m), e1 = expf(r1.y - m);
            float e2 = expf(r2.y - m), e3 = expf(r3.y - m);
            out[(size_t)(mb0 + mb) * 32 + tid] =
                (r0.x * e0 + r1.x * e1 + r2.x * e2 + r3.x * e3) / (e0 + e1 + e2 + e3);
        }
    }
}

// ---------------- launch ----------------
extern "C" void kernel_launch(void* const* d_in, const int* in_sizes, int n_in,
                              void* d_out, int out_size) {
    const float* feat     = (const float*)d_in[0];
    const float* coord    = (const float*)d_in[1];
    const float* hr_guide = (const float*)d_in[2];
    const float* lr_guide = (const float*)d_in[3];
    const float* w1 = (const float*)d_in[4];
    const float* b1 = (const float*)d_in[5];
    const float* w2 = (const float*)d_in[6];
    const float* b2 = (const float*)d_in[7];
    const float* w3 = (const float*)d_in[8];
    const float* b3 = (const float*)d_in[9];
    const float* w4 = (const float*)d_in[10];
    const float* b4 = (const float*)d_in[11];
    const float* w5 = (const float*)d_in[12];
    const float* b5 = (const float*)d_in[13];
    float* out = (float*)d_out;

    constexpr int SMEM_L13 = 2 * (32768 + 65536) + 4096;   // 200704
    constexpr int SMEM_L4  = 2 * (32768 + 32768) + 4096;   // 135168
    cudaFuncSetAttribute(layer_k<1>, cudaFuncAttributeMaxDynamicSharedMemorySize, SMEM_L13);
    cudaFuncSetAttribute(layer_k<2>, cudaFuncAttributeMaxDynamicSharedMemorySize, SMEM_L13);
    cudaFuncSetAttribute(layer_k<3>, cudaFuncAttributeMaxDynamicSharedMemorySize, SMEM_L13);
    cudaFuncSetAttribute(layer_k<4>, cudaFuncAttributeMaxDynamicSharedMemorySize, SMEM_L4);

    // weight blob prep (once)
    prep_w<<<(4 * 7  * 32 * 128 + 255) / 256, 256>>>(w1, 386,  1024, 4, 32, 7,  1);
    prep_w<<<(2 * 16 * 32 * 128 + 255) / 256, 256>>>(w2, 1024, 512,  2, 32, 16, 2);
    prep_w<<<(1 * 8  * 32 * 128 + 255) / 256, 256>>>(w3, 512,  256,  1, 32, 8,  3);
    prep_w<<<(1 * 4  * 16 * 128 + 255) / 256, 256>>>(w4, 256,  128,  1, 16, 4,  4);

    // pipeline over 16 chunks of 256 m-blocks
    for (int c = 0; c < MB / CH; ++c) {
        int mb0 = c * CH;
        gather_k<<<CH, NTH>>>(feat, coord, hr_guide, lr_guide, mb0);
        layer_k<1><<<dim3(CH, 4), NTH, SMEM_L13>>>(b1, nullptr, nullptr, nullptr, mb0);
        layer_k<2><<<dim3(CH, 2), NTH, SMEM_L13>>>(b2, nullptr, nullptr, nullptr, mb0);
        layer_k<3><<<dim3(CH, 1), NTH, SMEM_L13>>>(b3, nullptr, nullptr, nullptr, mb0);
        layer_k<4><<<dim3(CH, 1), NTH, SMEM_L4>>>(b4, w5, b5, out, mb0);
    }
}